// round 7
// baseline (speedup 1.0000x reference)
#include <cuda_runtime.h>
#include <cstdint>

// ---------------------------------------------------------------------------
// LSTM Neural Hawkes Process NLL  (B=64, L=1024, H=64)
// R7: FUSED scan+MC. R3 scan skeleton (proven fastest); the 12 producer
// warps compute the Monte-Carlo intensity integral for site l inside the
// arrive(1)->sync(2) wait window (previously idle). Warp 6 prefetches
// threefry uniforms 2 steps ahead; warp 7 owns the event log-term.
// No global state traffic at all: scan emits one float per batch.
// ---------------------------------------------------------------------------

#define BATCH   64
#define MAXL    1024
#define LP1     1025
#define HID     64
#define SEVENH  448
#define NMC     30
#define T_END   100.0f
#define EPS_L   1e-10f
#define TOTAL   (BATCH * LP1)          // 65600
#define LOG2E   1.4426950408889634f
#define LN2     0.6931471805599453f

// ------------------------- device scratch (no mallocs) ---------------------
__device__ float g_part[BATCH];

// ------------------------------ fast math -----------------------------------
__device__ __forceinline__ float ex2f(float x){ float y; asm("ex2.approx.f32 %0,%1;":"=f"(y):"f"(x)); return y; }
__device__ __forceinline__ float lg2f(float x){ float y; asm("lg2.approx.f32 %0,%1;":"=f"(y):"f"(x)); return y; }
__device__ __forceinline__ float tanh_mufu(float x){ float y; asm("tanh.approx.f32 %0,%1;":"=f"(y):"f"(x)); return y; }
__device__ __forceinline__ float fsoftplus(float x){
    return fmaxf(x, 0.0f) + LN2 * lg2f(1.0f + ex2f(-fabsf(x) * LOG2E));
}
__device__ __forceinline__ float flog(float x){ return LN2 * lg2f(x); }

// ------------------------------ packed f32x2 --------------------------------
__device__ __forceinline__ void fma2(unsigned long long& d, unsigned long long a, unsigned long long b){
    asm("fma.rn.f32x2 %0, %1, %2, %0;" : "+l"(d) : "l"(a), "l"(b));
}
__device__ __forceinline__ void add2(unsigned long long& d, unsigned long long a){
    asm("add.rn.f32x2 %0, %1, %0;" : "+l"(d) : "l"(a));
}
__device__ __forceinline__ unsigned long long pack2(float lo, float hi){
    unsigned long long r; asm("mov.b64 %0, {%1,%2};" : "=l"(r) : "f"(lo), "f"(hi)); return r;
}
__device__ __forceinline__ float2 unpack2(unsigned long long v){
    float2 r; asm("mov.b64 {%0,%1}, %2;" : "=f"(r.x), "=f"(r.y) : "l"(v)); return r;
}

// ------------------------------ named barriers ------------------------------
#define BAR_SYNC(id)   asm volatile("bar.sync %0, %1;"   :: "r"(id), "r"(SEVENH) : "memory")
#define BAR_ARRIVE(id) asm volatile("bar.arrive %0, %1;" :: "r"(id), "r"(SEVENH) : "memory")

// ------------------------------ Threefry-2x32-20 ----------------------------
__device__ __forceinline__ uint32_t rotl32(uint32_t x, int r){ return (x << r) | (x >> (32 - r)); }
__device__ __forceinline__ float tf_uniform(uint32_t flat){
    // JAX partitionable threefry, key (0,42): bits = out0 ^ out1
    uint32_t k0 = 0u, k1 = 42u, ks2 = k0 ^ k1 ^ 0x1BD11BDAu;
    uint32_t x0 = 0u + k0, x1 = flat + k1;
#define TF_R(r) { x0 += x1; x1 = rotl32(x1, (r)); x1 ^= x0; }
    TF_R(13) TF_R(15) TF_R(26) TF_R(6)   x0 += k1;  x1 += ks2 + 1u;
    TF_R(17) TF_R(29) TF_R(16) TF_R(24)  x0 += ks2; x1 += k0  + 2u;
    TF_R(13) TF_R(15) TF_R(26) TF_R(6)   x0 += k0;  x1 += k1  + 3u;
    TF_R(17) TF_R(29) TF_R(16) TF_R(24)  x0 += k1;  x1 += ks2 + 4u;
    TF_R(13) TF_R(15) TF_R(26) TF_R(6)   x0 += ks2; x1 += k0  + 5u;
#undef TF_R
    uint32_t bits = x0 ^ x1;
    return __uint_as_float((bits >> 9) | 0x3F800000u) - 1.0f;
}

// 65-long packed-f32x2 column dot against shared h
__device__ __forceinline__ float col_dot(const float* sh, const unsigned long long* w2,
                                         float w0, float bj, float dt)
{
    unsigned long long a0 = 0ull, a1 = 0ull, a2 = 0ull, a3 = 0ull;
    const ulonglong2* h2 = reinterpret_cast<const ulonglong2*>(sh);
#pragma unroll
    for (int q = 0; q < 4; q++) {
        ulonglong2 u = h2[2*q], v = h2[2*q + 1];
        fma2(a0, w2[4*q + 0],  u.x);
        fma2(a1, w2[4*q + 1],  u.y);
        fma2(a2, w2[4*q + 2],  v.x);
        fma2(a3, w2[4*q + 3],  v.y);
        ulonglong2 s = h2[2*q + 8], t = h2[2*q + 9];
        fma2(a0, w2[4*q + 16], s.x);
        fma2(a1, w2[4*q + 17], s.y);
        fma2(a2, w2[4*q + 18], t.x);
        fma2(a3, w2[4*q + 19], t.y);
    }
    add2(a0, a1); add2(a2, a3); add2(a0, a2);
    float2 r = unpack2(a0);
    return (r.x + r.y) + fmaf(w0, dt, bj);
}

// one MC sample: 64-channel intensity dot at random time u*dt (warp-collective)
__device__ __forceinline__ float mc_dot(const float4* st, float u, int lane)
{
    const float4 t0 = st[lane], t1 = st[lane + 32];
    float d = fmaf(t0.w, tanh_mufu(fmaf(t0.y, ex2f(u * t0.x), t0.z)),
                   t1.w * tanh_mufu(fmaf(t1.y, ex2f(u * t1.x), t1.z)));
#pragma unroll
    for (int off = 16; off; off >>= 1)
        d += __shfl_xor_sync(0xFFFFFFFFu, d, off);
    return d;
}

// ------------------------------ fused kernel ---------------------------------
// One CTA per batch, 448 threads. Warps 0-11 = GEMM producers + MC workers
// (warp 6 also RNG-prefetch, warp 7 also event-term). Warps 12-13 = gate-6
// columns + epilogue + MC parameter staging.
__global__ void __launch_bounds__(SEVENH, 1)
fused_kernel(const float* __restrict__ seq,    // [B, L, 1]
             const float* __restrict__ Wrec,   // [65, 448]
             const float* __restrict__ brec,   // [448]
             const float* __restrict__ Wf,     // [64]
             const float* __restrict__ bf,     // [1]
             const int*   __restrict__ lens)   // [B]
{
    __shared__ __align__(16) float  s_h[HID];
    __shared__ float  s_v[384];                // gates 0..5
    __shared__ float  s_dt[LP1];
    __shared__ __align__(16) float4 s_mc[2][HID];  // {m, A, cbar, o*wf} per site
    __shared__ float  s_bw[2][HID];            // before*wf per site
    __shared__ float  s_u[4][32];              // uniform ring (site & 3)
    __shared__ float  s_red[16];

    const int b    = blockIdx.x;
    const int j    = threadIdx.x;
    const int w    = j >> 5;
    const int lane = j & 31;
    const int len  = lens[b];
    const float bfv = bf[0];
    const float* sp = seq + b * MAXL;

    for (int l = j; l <= MAXL; l += SEVENH) {
        float v;
        if (l < len)        v = (l == 0) ? sp[0] : sp[l] - sp[l - 1];
        else if (l == len)  v = T_END - sp[len - 1];
        else                v = -1.0f;
        s_dt[l] = v;
    }

    // site-0 staging = zero state (generic MC path then yields softplus(bf))
    if (j >= 384) {
        const int ch = j - 384;
        s_h[ch] = 0.0f;
        s_mc[0][ch] = make_float4(0.f, 0.f, 0.f, 0.f);
        s_bw[0][ch] = 0.0f;
    }
    // uniforms for sites 0 and 1
    if (w == 6 && lane < NMC)
        s_u[0][lane] = tf_uniform((uint32_t)lane * TOTAL + (uint32_t)(b * LP1 + 0));
    if (w == 8 && lane < NMC)
        s_u[1][lane] = tf_uniform((uint32_t)lane * TOTAL + (uint32_t)(b * LP1 + 1));

    // column weights: row 0 scalar + 32 packed f32x2 pairs
    const float w0 = Wrec[j];
    const float bj = brec[j];
    unsigned long long w2[32];
#pragma unroll
    for (int k = 0; k < 32; k++)
        w2[k] = pack2(Wrec[(2*k + 1) * SEVENH + j], Wrec[(2*k + 2) * SEVENH + j]);

    __syncthreads();

    if (j < 384) {
        // =============== producers: warps 0-11 (gates 0..5) ================
        // branchless nonlinearity: gate 2 -> tanh(x); others -> sigmoid(x)
        const int  gate = j >> 6;
        const float al = (gate == 2) ? 1.0f : 0.5f;
        const float be = (gate == 2) ? 1.0f : 0.5f;
        const float ga = (gate == 2) ? 0.0f : 0.5f;
        const int nsamp = (w < 6) ? 3 : 2;     // samples: w, w+12, (w+24)

        float accW = 0.0f, accEv = 0.0f, accEps = 0.0f;

        for (int l = 0; l < len; l++) {
            const float dtl = s_dt[l];

            // phase 1: column GEMM + nonlinearity + publish
            const float acc = col_dot(s_h, w2, w0, bj, dtl);
            s_v[j] = fmaf(al, tanh_mufu(be * acc), ga);
            BAR_ARRIVE(1);

            // ---- MC for site l fills the epilogue wait window ----
            const float4* st = s_mc[l & 1];
            const float*  ur = s_u[l & 3];
            float sps = fsoftplus(mc_dot(st, ur[w], lane) + bfv);
            sps      += fsoftplus(mc_dot(st, ur[w + 12], lane) + bfv);
            if (nsamp == 3)
                sps  += fsoftplus(mc_dot(st, ur[w + 24], lane) + bfv);
            accW = fmaf(sps, dtl, accW);

            if (w == 7) {                      // event log-term for site l
                const float* bw = s_bw[l & 1];
                float q = bw[lane] + bw[lane + 32];
#pragma unroll
                for (int off = 16; off; off >>= 1)
                    q += __shfl_xor_sync(0xFFFFFFFFu, q, off);
                accEv += flog(fsoftplus(q + bfv) + EPS_L);
                accEps += dtl;
            }
            if (w == 6 && lane < NMC)          // prefetch uniforms, site l+2
                s_u[(l + 2) & 3][lane] =
                    tf_uniform((uint32_t)lane * TOTAL + (uint32_t)(b * LP1 + l + 2));

            BAR_SYNC(2);                       // h(l+1) ready
        }

        // ---- tail: MC for site len (integral only, no event term) ----
        {
            const float dtl = s_dt[len];
            const float4* st = s_mc[len & 1];
            const float*  ur = s_u[len & 3];
            float sps = fsoftplus(mc_dot(st, ur[w], lane) + bfv);
            sps      += fsoftplus(mc_dot(st, ur[w + 12], lane) + bfv);
            if (nsamp == 3)
                sps  += fsoftplus(mc_dot(st, ur[w + 24], lane) + bfv);
            accW = fmaf(sps, dtl, accW);
            if (w == 7) accEps += dtl;
        }

        if (lane == 0) s_red[w] = accW;
        if (w == 7 && lane == 0) { s_red[12] = accEv; s_red[13] = accEps; }
    } else {
        // ============ epilogue: warps 12,13 (= gate-6 columns) =============
        const int ch = j - 384;
        const float wfc = Wf[ch];
        float ct = 0.0f, cbar = 0.0f;

        for (int l = 0; l < len; l++) {
            // own gate-6 column: decay + exp factor (pre-barrier)
            const float acc = col_dot(s_h, w2, w0, bj, s_dt[l]);
            const float dec = fsoftplus(acc);
            const float dtn = s_dt[l + 1];
            const float e   = ex2f(-dec * dtn * LOG2E);

            BAR_SYNC(1);                       // wait gates
            const float iG = s_v[ch],        fG = s_v[ 64 + ch];
            const float zG = s_v[128 + ch],  oG = s_v[192 + ch];
            const float ib = s_v[256 + ch],  fb = s_v[320 + ch];
            const float c  = fmaf(fG, ct, iG * zG);
            const float cb = fmaf(fb, cbar, ib * zG);
            const float cd = fmaf(c - cb, e, cb);
            const float bef = oG * tanh_mufu(cd);
            ct = cd; cbar = cb;
            s_h[ch] = bef;
            // stage MC params for site l+1
            const int p = (l + 1) & 1;
            s_mc[p][ch] = make_float4(-dec * dtn * LOG2E, c - cb, cb, oG * wfc);
            s_bw[p][ch] = bef * wfc;
            BAR_ARRIVE(2);                     // h + staging released
        }
    }

    __syncthreads();
    if (j == 0) {
        float S = 0.0f;
#pragma unroll
        for (int k = 0; k < 12; k++) S += s_red[k];
        // loglike_b = sum(ev) - [ sum_l mean_s(softplus)*dt + EPS*sum_l dt ]
        g_part[b] = s_red[12] - (S * (1.0f / NMC) + EPS_L * s_red[13]);
    }
}

// --------------------------- final reduction ---------------------------------
__global__ void __launch_bounds__(32, 1)
reduce_kernel(float* __restrict__ out)
{
    const int lane = threadIdx.x;
    float s = g_part[lane] + g_part[lane + 32];
#pragma unroll
    for (int off = 16; off; off >>= 1)
        s += __shfl_xor_sync(0xFFFFFFFFu, s, off);
    if (lane == 0) out[0] = -s * (1.0f / BATCH);
}

// ------------------------------- launcher ------------------------------------
extern "C" void kernel_launch(void* const* d_in, const int* in_sizes, int n_in,
                              void* d_out, int out_size)
{
    const float* seq  = nullptr;
    const float* Wrec = nullptr;
    const float* brec = nullptr;
    const float* Wf   = nullptr;
    const float* bf   = nullptr;
    const int*   lens = nullptr;
    for (int i = 0; i < n_in; i++) {
        const int s = in_sizes[i];
        if      (s == BATCH * MAXL)     seq  = (const float*)d_in[i];
        else if (s == 65 * SEVENH)      Wrec = (const float*)d_in[i];
        else if (s == SEVENH)           brec = (const float*)d_in[i];
        else if (s == 1)                bf   = (const float*)d_in[i];
        else if (s == HID) {
            if (!Wf) Wf = (const float*)d_in[i];
            else     lens = (const int*)d_in[i];
        }
    }

    fused_kernel<<<BATCH, SEVENH>>>(seq, Wrec, brec, Wf, bf, lens);
    reduce_kernel<<<1, 32>>>((float*)d_out);
}

// round 8
// speedup vs baseline: 1.3676x; 1.3676x over previous
#include <cuda_runtime.h>
#include <cstdint>

// ---------------------------------------------------------------------------
// LSTM Neural Hawkes Process NLL  (B=64, L=1024, H=64)
// R8: R3 scan (proven) + MC consumer CTAs on SEPARATE SMs, one launch.
// Grid 128: CTA b<64 = scan for batch b; CTA 64+b = MC consumer for batch b.
// Epilogue publishes per-site state via release-RED on a per-batch u64
// counter; consumer warps acquire-poll and process sites w, w+14, ...
// ---------------------------------------------------------------------------

#define BATCH   64
#define MAXL    1024
#define LP1     1025
#define HID     64
#define SEVENH  448
#define NMC     30
#define T_END   100.0f
#define EPS_L   1e-10f
#define TOTAL   (BATCH * LP1)          // 65600
#define LOG2E   1.4426950408889634f
#define LN2     0.6931471805599453f

// ------------------------- device scratch (no mallocs) ---------------------
__device__ float4 g_state [TOTAL * HID];        // {c, cbar, o, dec}
__device__ float  g_before[TOTAL * HID];
__device__ unsigned long long g_ctr[BATCH];     // monotone publish counters
__device__ float  g_part[BATCH];

// ------------------------------ fast math -----------------------------------
__device__ __forceinline__ float ex2f(float x){ float y; asm("ex2.approx.f32 %0,%1;":"=f"(y):"f"(x)); return y; }
__device__ __forceinline__ float lg2f(float x){ float y; asm("lg2.approx.f32 %0,%1;":"=f"(y):"f"(x)); return y; }
__device__ __forceinline__ float tanh_mufu(float x){ float y; asm("tanh.approx.f32 %0,%1;":"=f"(y):"f"(x)); return y; }
__device__ __forceinline__ float fsoftplus(float x){
    return fmaxf(x, 0.0f) + LN2 * lg2f(1.0f + ex2f(-fabsf(x) * LOG2E));
}
__device__ __forceinline__ float flog(float x){ return LN2 * lg2f(x); }

// ------------------------------ packed f32x2 --------------------------------
__device__ __forceinline__ void fma2(unsigned long long& d, unsigned long long a, unsigned long long b){
    asm("fma.rn.f32x2 %0, %1, %2, %0;" : "+l"(d) : "l"(a), "l"(b));
}
__device__ __forceinline__ void add2(unsigned long long& d, unsigned long long a){
    asm("add.rn.f32x2 %0, %1, %0;" : "+l"(d) : "l"(a));
}
__device__ __forceinline__ unsigned long long pack2(float lo, float hi){
    unsigned long long r; asm("mov.b64 %0, {%1,%2};" : "=l"(r) : "f"(lo), "f"(hi)); return r;
}
__device__ __forceinline__ float2 unpack2(unsigned long long v){
    float2 r; asm("mov.b64 {%0,%1}, %2;" : "=f"(r.x), "=f"(r.y) : "l"(v)); return r;
}

// --------------------------- publish primitives ------------------------------
__device__ __forceinline__ void red_release_add1(unsigned long long* p){
    asm volatile("red.release.gpu.global.add.u64 [%0], 1;" :: "l"(p) : "memory");
}
__device__ __forceinline__ unsigned long long ld_acquire_u64(const unsigned long long* p){
    unsigned long long v;
    asm volatile("ld.acquire.gpu.global.u64 %0, [%1];" : "=l"(v) : "l"(p) : "memory");
    return v;
}

// ------------------------------ named barriers ------------------------------
#define BAR_SYNC(id)   asm volatile("bar.sync %0, %1;"   :: "r"(id), "r"(SEVENH) : "memory")
#define BAR_ARRIVE(id) asm volatile("bar.arrive %0, %1;" :: "r"(id), "r"(SEVENH) : "memory")

// ------------------------------ Threefry-2x32-20 ----------------------------
__device__ __forceinline__ uint32_t rotl32(uint32_t x, int r){ return (x << r) | (x >> (32 - r)); }
__device__ __forceinline__ float tf_uniform(uint32_t flat){
    // JAX partitionable threefry, key (0,42): bits = out0 ^ out1
    uint32_t k0 = 0u, k1 = 42u, ks2 = k0 ^ k1 ^ 0x1BD11BDAu;
    uint32_t x0 = 0u + k0, x1 = flat + k1;
#define TF_R(r) { x0 += x1; x1 = rotl32(x1, (r)); x1 ^= x0; }
    TF_R(13) TF_R(15) TF_R(26) TF_R(6)   x0 += k1;  x1 += ks2 + 1u;
    TF_R(17) TF_R(29) TF_R(16) TF_R(24)  x0 += ks2; x1 += k0  + 2u;
    TF_R(13) TF_R(15) TF_R(26) TF_R(6)   x0 += k0;  x1 += k1  + 3u;
    TF_R(17) TF_R(29) TF_R(16) TF_R(24)  x0 += k1;  x1 += ks2 + 4u;
    TF_R(13) TF_R(15) TF_R(26) TF_R(6)   x0 += ks2; x1 += k0  + 5u;
#undef TF_R
    uint32_t bits = x0 ^ x1;
    return __uint_as_float((bits >> 9) | 0x3F800000u) - 1.0f;
}

// 65-long packed-f32x2 column dot against shared h
__device__ __forceinline__ float col_dot(const float* sh, const unsigned long long* w2,
                                         float w0, float bj, float dt)
{
    unsigned long long a0 = 0ull, a1 = 0ull, a2 = 0ull, a3 = 0ull;
    const ulonglong2* h2 = reinterpret_cast<const ulonglong2*>(sh);
#pragma unroll
    for (int q = 0; q < 4; q++) {
        ulonglong2 u = h2[2*q], v = h2[2*q + 1];
        fma2(a0, w2[4*q + 0],  u.x);
        fma2(a1, w2[4*q + 1],  u.y);
        fma2(a2, w2[4*q + 2],  v.x);
        fma2(a3, w2[4*q + 3],  v.y);
        ulonglong2 s = h2[2*q + 8], t = h2[2*q + 9];
        fma2(a0, w2[4*q + 16], s.x);
        fma2(a1, w2[4*q + 17], s.y);
        fma2(a2, w2[4*q + 18], t.x);
        fma2(a3, w2[4*q + 19], t.y);
    }
    add2(a0, a1); add2(a2, a3); add2(a0, a2);
    float2 r = unpack2(a0);
    return (r.x + r.y) + fmaf(w0, dt, bj);
}

// --------------------------- shared memory union -----------------------------
union SmemU {
    struct {
        float h[HID];
        float v[384];
        float dt[LP1];
    } scan;
    struct {
        float4 stg[14][HID];    // per-warp transformed params
        float  red[32];
    } mc;
};

// ------------------------------- main kernel ---------------------------------
__global__ void __launch_bounds__(SEVENH, 1)
hawkes_kernel(const float* __restrict__ seq,    // [B, L, 1]
              const float* __restrict__ Wrec,   // [65, 448]
              const float* __restrict__ brec,   // [448]
              const float* __restrict__ Wf,     // [64]
              const float* __restrict__ bf,     // [1]
              const int*   __restrict__ lens)   // [B]
{
    __shared__ SmemU smem;

    const int j    = threadIdx.x;
    const int w    = j >> 5;
    const int lane = j & 31;

    if (blockIdx.x < BATCH) {
        // ====================== SCAN role (R3 skeleton) ======================
        const int b   = blockIdx.x;
        const int len = lens[b];
        const float* sp = seq + b * MAXL;
        float* s_h  = smem.scan.h;
        float* s_v  = smem.scan.v;
        float* s_dt = smem.scan.dt;

        for (int l = j; l <= MAXL; l += SEVENH) {
            float v;
            if (l < len)        v = (l == 0) ? sp[0] : sp[l] - sp[l - 1];
            else if (l == len)  v = T_END - sp[len - 1];
            else                v = -1.0f;
            s_dt[l] = v;
        }

        if (j >= 384) {                 // epilogue threads init state index 0
            const int ch = j - 384;
            s_h[ch] = 0.0f;
            g_state [(b * LP1) * HID + ch] = make_float4(0.f, 0.f, 0.f, 0.f);
            g_before[(b * LP1) * HID + ch] = 0.0f;
        }

        const float w0 = Wrec[j];
        const float bj = brec[j];
        unsigned long long w2[32];
#pragma unroll
        for (int k = 0; k < 32; k++)
            w2[k] = pack2(Wrec[(2*k + 1) * SEVENH + j], Wrec[(2*k + 2) * SEVENH + j]);

        __syncthreads();

        if (j < 384) {
            // ----- producers: warps 0-11 (gates 0..5), branchless nonlin -----
            const int  gate = j >> 6;
            const float al = (gate == 2) ? 1.0f : 0.5f;
            const float be = (gate == 2) ? 1.0f : 0.5f;
            const float ga = (gate == 2) ? 0.0f : 0.5f;
            for (int l = 0; l < len; l++) {
                const float acc = col_dot(s_h, w2, w0, bj, s_dt[l]);
                s_v[j] = fmaf(al, tanh_mufu(be * acc), ga);
                BAR_ARRIVE(1);
                BAR_SYNC(2);            // h(l+1) ready
            }
        } else {
            // ----- epilogue: warps 12,13 (= gate-6 columns) -----
            const int ch = j - 384;
            float ct = 0.0f, cbar = 0.0f;
            for (int l = 0; l < len; l++) {
                const float acc = col_dot(s_h, w2, w0, bj, s_dt[l]);
                const float dec = fsoftplus(acc);
                const float e   = ex2f(-dec * s_dt[l + 1] * LOG2E);

                BAR_SYNC(1);
                const float iG = s_v[ch],        fG = s_v[ 64 + ch];
                const float zG = s_v[128 + ch],  oG = s_v[192 + ch];
                const float ib = s_v[256 + ch],  fb = s_v[320 + ch];
                const float c  = fmaf(fG, ct, iG * zG);
                const float cb = fmaf(fb, cbar, ib * zG);
                const float cd = fmaf(c - cb, e, cb);
                const float bef = oG * tanh_mufu(cd);
                ct = cd; cbar = cb;
                s_h[ch] = bef;
                BAR_SYNC(2);            // releases producers

                // publish site l+1 (off critical path: producers already run)
                const int base = (b * LP1 + l + 1) * HID + ch;
                g_state [base] = make_float4(c, cb, oG, dec);
                g_before[base] = bef;
                red_release_add1(&g_ctr[b]);   // release orders THIS thread's STGs
            }
        }
    } else {
        // ===================== MC CONSUMER role ==============================
        const int b   = blockIdx.x - BATCH;
        const int len = lens[b];
        const float bfv = bf[0];
        const float* sp = seq + b * MAXL;
        const float wf0 = Wf[lane], wf1 = Wf[lane + 32];
        float4* stg = smem.mc.stg[w];

        float accInt = 0.0f, accEv = 0.0f;

        for (int s = w; s <= len; s += 14) {
            // wait until site s is published (ctr >= 64 * max(s,1))
            const unsigned long long tgt = 64ull * (unsigned long long)(s > 0 ? s : 1);
            while (ld_acquire_u64(&g_ctr[b]) < tgt) __nanosleep(128);

            // dt for site s (from inputs; all lanes redundantly)
            float dt;
            if (s < len) dt = (s == 0) ? sp[0] : sp[s] - sp[s - 1];
            else         dt = T_END - sp[len - 1];

            // stage transformed params {m, A, cbar, o*wf}
            const int base = (b * LP1 + s) * HID;
            const float4 s0 = g_state[base + lane];
            const float4 s1 = g_state[base + lane + 32];
            const float mscale = -dt * LOG2E;
            stg[lane]      = make_float4(s0.w * mscale, s0.x - s0.y, s0.y, s0.z * wf0);
            stg[lane + 32] = make_float4(s1.w * mscale, s1.x - s1.y, s1.y, s1.z * wf1);
            float q = 0.0f;
            if (s < len)
                q = fmaf(g_before[base + lane], wf0, g_before[base + lane + 32] * wf1);
            __syncwarp();

            // lane = MC sample: full 64-channel intensity at u_s * dt
            float spv = 0.0f;
            if (lane < NMC) {
                const float u = tf_uniform((uint32_t)lane * TOTAL + (uint32_t)(b * LP1 + s));
                float a0 = 0.0f, a1 = 0.0f;
#pragma unroll 8
                for (int ch = 0; ch < HID; ch += 2) {
                    const float4 t0 = stg[ch], t1 = stg[ch + 1];
                    a0 = fmaf(t0.w, tanh_mufu(fmaf(t0.y, ex2f(u * t0.x), t0.z)), a0);
                    a1 = fmaf(t1.w, tanh_mufu(fmaf(t1.y, ex2f(u * t1.x), t1.z)), a1);
                }
                spv = fsoftplus(a0 + a1 + bfv);
            }
#pragma unroll
            for (int off = 16; off; off >>= 1) {
                spv += __shfl_xor_sync(0xFFFFFFFFu, spv, off);
                q   += __shfl_xor_sync(0xFFFFFFFFu, q,   off);
            }
            if (lane == 0) {
                accInt = fmaf(spv * (1.0f / NMC) + EPS_L, dt, accInt);
                if (s < len) accEv += flog(fsoftplus(q + bfv) + EPS_L);
            }
            __syncwarp();               // protect stg for next site
        }

        if (lane == 0) {
            smem.mc.red[2*w]     = accInt;
            smem.mc.red[2*w + 1] = accEv;
        }
        __syncthreads();
        if (j == 0) {
            float SInt = 0.0f, SEv = 0.0f;
#pragma unroll
            for (int k = 0; k < 14; k++) { SInt += smem.mc.red[2*k]; SEv += smem.mc.red[2*k+1]; }
            g_part[b] = SEv - SInt;     // loglike_b
        }
    }
}

// --------------------------- final reduction ---------------------------------
__global__ void __launch_bounds__(32, 1)
reduce_kernel(float* __restrict__ out)
{
    const int lane = threadIdx.x;
    float s = g_part[lane] + g_part[lane + 32];
#pragma unroll
    for (int off = 16; off; off >>= 1)
        s += __shfl_xor_sync(0xFFFFFFFFu, s, off);
    if (lane == 0) out[0] = -s * (1.0f / BATCH);
}

// ------------------------------- launcher ------------------------------------
extern "C" void kernel_launch(void* const* d_in, const int* in_sizes, int n_in,
                              void* d_out, int out_size)
{
    const float* seq  = nullptr;
    const float* Wrec = nullptr;
    const float* brec = nullptr;
    const float* Wf   = nullptr;
    const float* bf   = nullptr;
    const int*   lens = nullptr;
    for (int i = 0; i < n_in; i++) {
        const int s = in_sizes[i];
        if      (s == BATCH * MAXL)     seq  = (const float*)d_in[i];
        else if (s == 65 * SEVENH)      Wrec = (const float*)d_in[i];
        else if (s == SEVENH)           brec = (const float*)d_in[i];
        else if (s == 1)                bf   = (const float*)d_in[i];
        else if (s == HID) {
            if (!Wf) Wf = (const float*)d_in[i];
            else     lens = (const int*)d_in[i];
        }
    }

    hawkes_kernel<<<2 * BATCH, SEVENH>>>(seq, Wrec, brec, Wf, bf, lens);
    reduce_kernel<<<1, 32>>>((float*)d_out);
}